// round 1
// baseline (speedup 1.0000x reference)
#include <cuda_runtime.h>
#include <cuda_bf16.h>

// Problem dims
#define U_LEN 2048
#define R_LEN 256
#define L_LEN 1024
#define M_LEN 512
#define D_DIM 1024
#define NHEAD 16
#define HDIM  64
#define QLEN  (U_LEN + R_LEN)                   // 2304
#define KVLEN (M_LEN + R_LEN + L_LEN + U_LEN)   // 3840
#define MR    (M_LEN + R_LEN)                   // 768

// Scratch (no cudaMalloc allowed)
__device__ float g_query[QLEN * D_DIM];
__device__ float g_attn [QLEN * D_DIM];

// ---------------------------------------------------------------------------
// Generic tiled GEMM: C = gather(A) @ W^T + bias
// MODE 0: A = concat(right_context, utterance) -> C = g_query (N=1024)
// MODE 1: A = concat(memory, right_context, utterance) -> scatter to key/value
// MODE 2: A = g_attn -> C = out (N=1024)
// BM=BN=64, BK=16, 16x16 threads, 4x4 microtile
// ---------------------------------------------------------------------------
template <int MODE>
__global__ void gemm_bias_kernel(const float* __restrict__ A0,   // utterance (or unused)
                                 const float* __restrict__ A1,   // right_context
                                 const float* __restrict__ A2,   // memory
                                 const float* __restrict__ W,    // [N, K] row-major
                                 const float* __restrict__ bias, // [N]
                                 float* __restrict__ C0,         // key (MODE1) / out (MODE2)
                                 float* __restrict__ C1,         // value (MODE1)
                                 int K)
{
    const int BM = 64, BN = 64, BK = 16;
    __shared__ float As[BK][BM + 1];
    __shared__ float Bs[BK][BN + 1];

    const int bm = blockIdx.y, bn = blockIdx.x;
    const int tx = threadIdx.x, ty = threadIdx.y;
    const int tid = ty * 16 + tx;

    float acc[4][4];
#pragma unroll
    for (int i = 0; i < 4; i++)
#pragma unroll
        for (int j = 0; j < 4; j++) acc[i][j] = 0.f;

    for (int k0 = 0; k0 < K; k0 += BK) {
        // ---- load A tile (with row gather) ----
#pragma unroll
        for (int i = 0; i < 4; i++) {
            int idx = tid + i * 256;
            int ar = idx / BK, ac = idx % BK;
            int row = bm * BM + ar;
            const float* src;
            if (MODE == 0) {
                src = (row < R_LEN) ? (A1 + (size_t)row * D_DIM)
                                    : (A0 + (size_t)(row - R_LEN) * D_DIM);
            } else if (MODE == 1) {
                src = (row < M_LEN) ? (A2 + (size_t)row * D_DIM)
                    : (row < MR)    ? (A1 + (size_t)(row - M_LEN) * D_DIM)
                                    : (A0 + (size_t)(row - MR) * D_DIM);
            } else {
                src = g_attn + (size_t)row * D_DIM;
            }
            As[ac][ar] = src[k0 + ac];
        }
        // ---- load W tile ----
#pragma unroll
        for (int i = 0; i < 4; i++) {
            int idx = tid + i * 256;
            int br = idx / BK, bc = idx % BK;
            Bs[bc][br] = W[(size_t)(bn * BN + br) * K + k0 + bc];
        }
        __syncthreads();

#pragma unroll
        for (int kk = 0; kk < BK; kk++) {
            float ra[4], rb[4];
#pragma unroll
            for (int i = 0; i < 4; i++) ra[i] = As[kk][ty * 4 + i];
#pragma unroll
            for (int j = 0; j < 4; j++) rb[j] = Bs[kk][tx * 4 + j];
#pragma unroll
            for (int i = 0; i < 4; i++)
#pragma unroll
                for (int j = 0; j < 4; j++) acc[i][j] += ra[i] * rb[j];
        }
        __syncthreads();
    }

    // ---- epilogue ----
#pragma unroll
    for (int i = 0; i < 4; i++) {
        int row = bm * BM + ty * 4 + i;
#pragma unroll
        for (int j = 0; j < 4; j++) {
            int col = bn * BN + tx * 4 + j;
            float v = acc[i][j] + bias[col];
            if (MODE == 0) {
                g_query[(size_t)row * D_DIM + col] = v;
            } else if (MODE == 1) {
                int krow = (row < MR) ? row : row + L_LEN;
                if (col < D_DIM) C0[(size_t)krow * D_DIM + col] = v;
                else             C1[(size_t)krow * D_DIM + (col - D_DIM)] = v;
            } else {
                C0[(size_t)row * D_DIM + col] = v;
            }
        }
    }
}

// ---------------------------------------------------------------------------
// Flash-attention (fp32). One thread = one query row. K/V tiles in SMEM.
// grid: (NHEAD, QLEN/BQ), block: BQ threads
// ---------------------------------------------------------------------------
#define BQ 128
#define TK 32

__global__ __launch_bounds__(BQ, 1)
void attn_kernel(const float* __restrict__ key,
                 const float* __restrict__ value)
{
    const int h  = blockIdx.x;
    const int q  = blockIdx.y * BQ + threadIdx.x;
    const int t  = threadIdx.x;
    const float scale = 0.125f; // 64^-0.5

    __shared__ float4 Ksh[TK][HDIM / 4];
    __shared__ float4 Vsh[TK][HDIM / 4];

    float4 qreg[16];
    const float4* qptr = (const float4*)(g_query + (size_t)q * D_DIM + h * HDIM);
#pragma unroll
    for (int i = 0; i < 16; i++) qreg[i] = qptr[i];

    float4 acc[16];
#pragma unroll
    for (int i = 0; i < 16; i++) acc[i] = make_float4(0.f, 0.f, 0.f, 0.f);
    float m = -1e30f, l = 0.f;

    for (int kv0 = 0; kv0 < KVLEN; kv0 += TK) {
        // cooperative tile load: TK*16 = 512 float4 each for K and V
#pragma unroll
        for (int i = 0; i < 4; i++) {
            int idx = t + i * BQ;
            int r = idx / 16, c = idx % 16;
            Ksh[r][c] = *(const float4*)(key   + (size_t)(kv0 + r) * D_DIM + h * HDIM + c * 4);
            Vsh[r][c] = *(const float4*)(value + (size_t)(kv0 + r) * D_DIM + h * HDIM + c * 4);
        }
        __syncthreads();

        float s[TK];
        float mt = -1e30f;
#pragma unroll
        for (int j = 0; j < TK; j++) {
            float a = 0.f;
#pragma unroll
            for (int c = 0; c < 16; c++) {
                float4 k4 = Ksh[j][c];
                a += qreg[c].x * k4.x + qreg[c].y * k4.y +
                     qreg[c].z * k4.z + qreg[c].w * k4.w;
            }
            s[j] = a * scale;
            mt = fmaxf(mt, s[j]);
        }
        float mnew = fmaxf(m, mt);
        float corr = __expf(m - mnew);
        l *= corr;
#pragma unroll
        for (int i = 0; i < 16; i++) {
            acc[i].x *= corr; acc[i].y *= corr;
            acc[i].z *= corr; acc[i].w *= corr;
        }
#pragma unroll
        for (int j = 0; j < TK; j++) {
            float p = __expf(s[j] - mnew);
            l += p;
#pragma unroll
            for (int c = 0; c < 16; c++) {
                float4 v4 = Vsh[j][c];
                acc[c].x += p * v4.x; acc[c].y += p * v4.y;
                acc[c].z += p * v4.z; acc[c].w += p * v4.w;
            }
        }
        m = mnew;
        __syncthreads();
    }

    float inv = 1.f / l;
    float4* outp = (float4*)(g_attn + (size_t)q * D_DIM + h * HDIM);
#pragma unroll
    for (int i = 0; i < 16; i++) {
        outp[i] = make_float4(acc[i].x * inv, acc[i].y * inv,
                              acc[i].z * inv, acc[i].w * inv);
    }
}

// ---------------------------------------------------------------------------
extern "C" void kernel_launch(void* const* d_in, const int* in_sizes, int n_in,
                              void* d_out, int out_size)
{
    const float* utter = (const float*)d_in[0];
    const float* rctx  = (const float*)d_in[1];
    const float* mem   = (const float*)d_in[2];
    const float* lck   = (const float*)d_in[3];
    const float* lcv   = (const float*)d_in[4];
    const float* Wq    = (const float*)d_in[5];
    const float* bq    = (const float*)d_in[6];
    const float* Wkv   = (const float*)d_in[7];
    const float* bkv   = (const float*)d_in[8];
    const float* Wo    = (const float*)d_in[9];
    const float* bo    = (const float*)d_in[10];

    float* out = (float*)d_out;                       // [2304, 1024]
    float* key = out + (size_t)QLEN * D_DIM;          // [3840, 1024]
    float* val = key + (size_t)KVLEN * D_DIM;         // [3840, 1024]

    dim3 blk(16, 16);

    // 1) query projection: [2304,1024] = q_in @ Wq^T + bq
    gemm_bias_kernel<0><<<dim3(D_DIM / 64, QLEN / 64), blk>>>(
        utter, rctx, nullptr, Wq, bq, nullptr, nullptr, D_DIM);

    // 2) kv projection: [2816,2048] = kv_in @ Wkv^T + bkv, scattered to key/value
    gemm_bias_kernel<1><<<dim3(2 * D_DIM / 64, (MR + U_LEN) / 64), blk>>>(
        utter, rctx, mem, Wkv, bkv, key, val, D_DIM);

    // 3) splice in left context (contiguous regions)
    cudaMemcpyAsync(key + (size_t)MR * D_DIM, lck,
                    (size_t)L_LEN * D_DIM * sizeof(float),
                    cudaMemcpyDeviceToDevice, 0);
    cudaMemcpyAsync(val + (size_t)MR * D_DIM, lcv,
                    (size_t)L_LEN * D_DIM * sizeof(float),
                    cudaMemcpyDeviceToDevice, 0);

    // 4) attention -> g_attn
    attn_kernel<<<dim3(NHEAD, QLEN / BQ), BQ>>>(key, val);

    // 5) output projection: out = g_attn @ Wo^T + bo
    gemm_bias_kernel<2><<<dim3(D_DIM / 64, QLEN / 64), blk>>>(
        nullptr, nullptr, nullptr, Wo, bo, out, nullptr, D_DIM);
}

// round 2
// speedup vs baseline: 1.5123x; 1.5123x over previous
#include <cuda_runtime.h>
#include <cuda_bf16.h>

// Problem dims
#define U_LEN 2048
#define R_LEN 256
#define L_LEN 1024
#define M_LEN 512
#define D_DIM 1024
#define NHEAD 16
#define HDIM  64
#define QLEN  (U_LEN + R_LEN)                   // 2304
#define KVLEN (M_LEN + R_LEN + L_LEN + U_LEN)   // 3840
#define MR    (M_LEN + R_LEN)                   // 768

typedef unsigned long long ull;

// Scratch (no cudaMalloc allowed)
__device__ float g_query[QLEN * D_DIM];
__device__ float g_attn [QLEN * D_DIM];

// ---------------------------------------------------------------------------
// helpers
// ---------------------------------------------------------------------------
__device__ __forceinline__ unsigned f2tf32(float f) {
    unsigned r;
    asm("cvt.rna.tf32.f32 %0, %1;" : "=r"(r) : "f"(f));
    return r;
}

__device__ __forceinline__ void mma_tf32(float* d, const unsigned* a, const unsigned* b) {
    asm volatile(
        "mma.sync.aligned.m16n8k8.row.col.f32.tf32.tf32.f32 "
        "{%0,%1,%2,%3}, {%4,%5,%6,%7}, {%8,%9}, {%0,%1,%2,%3};"
        : "+f"(d[0]), "+f"(d[1]), "+f"(d[2]), "+f"(d[3])
        : "r"(a[0]), "r"(a[1]), "r"(a[2]), "r"(a[3]), "r"(b[0]), "r"(b[1]));
}

#define FMA2(d, a, b, c) \
    asm("fma.rn.f32x2 %0, %1, %2, %3;" : "=l"(d) : "l"(a), "l"(b), "l"(c))
#define MUL2(d, a, b) \
    asm("mul.rn.f32x2 %0, %1, %2;" : "=l"(d) : "l"(a), "l"(b))

__device__ __forceinline__ ull pack2(float lo, float hi) {
    ull r;
    asm("mov.b64 %0, {%1,%2};" : "=l"(r) : "f"(lo), "f"(hi));
    return r;
}

__device__ __forceinline__ void cp16(void* s, const void* g) {
    unsigned sa = (unsigned)__cvta_generic_to_shared(s);
    asm volatile("cp.async.cg.shared.global [%0], [%1], 16;" :: "r"(sa), "l"(g));
}
#define CP_COMMIT() asm volatile("cp.async.commit_group;")
#define CP_WAIT0()  asm volatile("cp.async.wait_group 0;" ::: "memory")

// ---------------------------------------------------------------------------
// TF32 tensor-core GEMM: C[M,N] = gather(A)[M,K] @ W[N,K]^T + bias
// BM=128, BN=64, BK=16; 128 threads (4 warps), warp computes 32x64.
// MODE 0: A = concat(right, utter)        -> g_query
// MODE 1: A = concat(mem, right, utter)   -> scatter to key/value (N=2048)
// MODE 2: A = g_attn                      -> out
// ---------------------------------------------------------------------------
template <int MODE>
__global__ __launch_bounds__(128)
void gemm_tf32(const float* __restrict__ A0,   // utterance
               const float* __restrict__ A1,   // right_context
               const float* __restrict__ A2,   // memory
               const float* __restrict__ W,    // [N, K] row-major
               const float* __restrict__ bias, // [N]
               float* __restrict__ C0,
               float* __restrict__ C1)
{
    __shared__ unsigned As[128][20];   // BK=16 + pad 4 -> conflict-free frag loads
    __shared__ unsigned Bs[64][20];

    const int tid  = threadIdx.x;
    const int lane = tid & 31;
    const int warp = tid >> 5;
    const int bm = blockIdx.y, bn = blockIdx.x;
    const int K = D_DIM, KT = K / 16;
    const int tig = lane & 3, grp = lane >> 2;

    // A rows handled by this thread (4 float4 loads, row = t/4 + 32*i, col4 = t&3)
    const float* arow[4];
#pragma unroll
    for (int i = 0; i < 4; i++) {
        int row = bm * 128 + (tid >> 2) + 32 * i;
        if (MODE == 0) {
            arow[i] = (row < R_LEN) ? (A1 + (size_t)row * D_DIM)
                                    : (A0 + (size_t)(row - R_LEN) * D_DIM);
        } else if (MODE == 1) {
            arow[i] = (row < M_LEN) ? (A2 + (size_t)row * D_DIM)
                    : (row < MR)    ? (A1 + (size_t)(row - M_LEN) * D_DIM)
                                    : (A0 + (size_t)(row - MR) * D_DIM);
        } else {
            arow[i] = g_attn + (size_t)row * D_DIM;
        }
    }
    const float* wrow[2];
#pragma unroll
    for (int i = 0; i < 2; i++) {
        int row = bn * 64 + (tid >> 2) + 32 * i;
        wrow[i] = W + (size_t)row * K;
    }

    float acc[2][8][4];
#pragma unroll
    for (int mt = 0; mt < 2; mt++)
#pragma unroll
        for (int nt = 0; nt < 8; nt++)
#pragma unroll
            for (int i = 0; i < 4; i++) acc[mt][nt][i] = 0.f;

    float4 ra[4], rb[2];
    const int c4 = (tid & 3) * 4;

    // prologue: fetch tile 0
#pragma unroll
    for (int i = 0; i < 4; i++) ra[i] = *(const float4*)(arow[i] + c4);
#pragma unroll
    for (int i = 0; i < 2; i++) rb[i] = *(const float4*)(wrow[i] + c4);
#pragma unroll
    for (int i = 0; i < 4; i++) {
        int r = (tid >> 2) + 32 * i;
        As[r][c4] = f2tf32(ra[i].x); As[r][c4 + 1] = f2tf32(ra[i].y);
        As[r][c4 + 2] = f2tf32(ra[i].z); As[r][c4 + 3] = f2tf32(ra[i].w);
    }
#pragma unroll
    for (int i = 0; i < 2; i++) {
        int r = (tid >> 2) + 32 * i;
        Bs[r][c4] = f2tf32(rb[i].x); Bs[r][c4 + 1] = f2tf32(rb[i].y);
        Bs[r][c4 + 2] = f2tf32(rb[i].z); Bs[r][c4 + 3] = f2tf32(rb[i].w);
    }
    __syncthreads();

    for (int kt = 0; kt < KT; kt++) {
        // prefetch next tile into registers (overlaps with mma below)
        if (kt + 1 < KT) {
            int k0 = (kt + 1) * 16;
#pragma unroll
            for (int i = 0; i < 4; i++) ra[i] = *(const float4*)(arow[i] + k0 + c4);
#pragma unroll
            for (int i = 0; i < 2; i++) rb[i] = *(const float4*)(wrow[i] + k0 + c4);
        }
        // compute current tile
#pragma unroll
        for (int ks = 0; ks < 2; ks++) {
            int kk = ks * 8;
            unsigned b[8][2];
#pragma unroll
            for (int nt = 0; nt < 8; nt++) {
                b[nt][0] = Bs[nt * 8 + grp][kk + tig];
                b[nt][1] = Bs[nt * 8 + grp][kk + tig + 4];
            }
#pragma unroll
            for (int mt = 0; mt < 2; mt++) {
                unsigned a[4];
                int r0 = warp * 32 + mt * 16 + grp;
                a[0] = As[r0][kk + tig];     a[1] = As[r0 + 8][kk + tig];
                a[2] = As[r0][kk + tig + 4]; a[3] = As[r0 + 8][kk + tig + 4];
#pragma unroll
                for (int nt = 0; nt < 8; nt++) mma_tf32(acc[mt][nt], a, b[nt]);
            }
        }
        __syncthreads();
        if (kt + 1 < KT) {
#pragma unroll
            for (int i = 0; i < 4; i++) {
                int r = (tid >> 2) + 32 * i;
                As[r][c4] = f2tf32(ra[i].x); As[r][c4 + 1] = f2tf32(ra[i].y);
                As[r][c4 + 2] = f2tf32(ra[i].z); As[r][c4 + 3] = f2tf32(ra[i].w);
            }
#pragma unroll
            for (int i = 0; i < 2; i++) {
                int r = (tid >> 2) + 32 * i;
                Bs[r][c4] = f2tf32(rb[i].x); Bs[r][c4 + 1] = f2tf32(rb[i].y);
                Bs[r][c4 + 2] = f2tf32(rb[i].z); Bs[r][c4 + 3] = f2tf32(rb[i].w);
            }
            __syncthreads();
        }
    }

    // epilogue
#pragma unroll
    for (int mt = 0; mt < 2; mt++) {
#pragma unroll
        for (int nt = 0; nt < 8; nt++) {
            int col = bn * 64 + nt * 8 + 2 * tig;
#pragma unroll
            for (int half = 0; half < 2; half++) {
                int row = bm * 128 + warp * 32 + mt * 16 + grp + half * 8;
                float v0 = acc[mt][nt][half * 2 + 0] + bias[col];
                float v1 = acc[mt][nt][half * 2 + 1] + bias[col + 1];
                if (MODE == 0) {
                    *(float2*)(g_query + (size_t)row * D_DIM + col) = make_float2(v0, v1);
                } else if (MODE == 1) {
                    int krow = (row < MR) ? row : row + L_LEN;
                    if (col < D_DIM)
                        *(float2*)(C0 + (size_t)krow * D_DIM + col) = make_float2(v0, v1);
                    else
                        *(float2*)(C1 + (size_t)krow * D_DIM + (col - D_DIM)) = make_float2(v0, v1);
                } else {
                    *(float2*)(C0 + (size_t)row * D_DIM + col) = make_float2(v0, v1);
                }
            }
        }
    }
}

// ---------------------------------------------------------------------------
// Flash-attention, fp32 with packed f32x2 FMA + cp.async double buffering.
// One thread = one query row. grid (NHEAD, QLEN/BQ), block BQ.
// ---------------------------------------------------------------------------
#define BQ 128
#define TK 32
#define NTILES (KVLEN / TK)   // 120

__global__ __launch_bounds__(BQ)
void attn_kernel(const float* __restrict__ key,
                 const float* __restrict__ value)
{
    __shared__ float Ksh[2][TK][HDIM];
    __shared__ float Vsh[2][TK][HDIM];

    const int h = blockIdx.x;
    const int q = blockIdx.y * BQ + threadIdx.x;
    const int t = threadIdx.x;

    // q row, pre-scaled, packed f32x2
    ull q2[32];
    {
        const ull* qp = (const ull*)(g_query + (size_t)q * D_DIM + h * HDIM);
        const ull sc2 = pack2(0.125f, 0.125f);
#pragma unroll
        for (int i = 0; i < 32; i++) { ull v = qp[i]; MUL2(q2[i], v, sc2); }
    }

    ull acc[32];
#pragma unroll
    for (int i = 0; i < 32; i++) acc[i] = 0ull;
    float m = -1e30f, l = 0.f;

    // tile loader: 4 cp.async 16B per thread for each of K, V
    const float* kbase = key   + (size_t)h * HDIM;
    const float* vbase = value + (size_t)h * HDIM;

    // prologue: tile 0 into buf 0
#pragma unroll
    for (int i = 0; i < 4; i++) {
        int idx = t + i * BQ;
        int r = idx >> 4, c = idx & 15;
        cp16(&Ksh[0][r][c * 4], kbase + (size_t)r * D_DIM + c * 4);
        cp16(&Vsh[0][r][c * 4], vbase + (size_t)r * D_DIM + c * 4);
    }
    CP_COMMIT();
    CP_WAIT0();
    __syncthreads();

    for (int tile = 0; tile < NTILES; tile++) {
        const int cur = tile & 1;
        if (tile + 1 < NTILES) {
            const float* kn = kbase + (size_t)(tile + 1) * TK * D_DIM;
            const float* vn = vbase + (size_t)(tile + 1) * TK * D_DIM;
#pragma unroll
            for (int i = 0; i < 4; i++) {
                int idx = t + i * BQ;
                int r = idx >> 4, c = idx & 15;
                cp16(&Ksh[cur ^ 1][r][c * 4], kn + (size_t)r * D_DIM + c * 4);
                cp16(&Vsh[cur ^ 1][r][c * 4], vn + (size_t)r * D_DIM + c * 4);
            }
        }
        CP_COMMIT();

        // ---- scores ----
        float s[TK];
        float mt = -1e30f;
#pragma unroll
        for (int j = 0; j < TK; j++) {
            const ulonglong2* K2 = (const ulonglong2*)Ksh[cur][j];
            ull d0 = 0ull, d1 = 0ull, d2 = 0ull, d3 = 0ull;
#pragma unroll
            for (int c = 0; c < 16; c += 2) {
                ulonglong2 ka = K2[c];
                ulonglong2 kb = K2[c + 1];
                FMA2(d0, q2[2 * c + 0], ka.x, d0);
                FMA2(d1, q2[2 * c + 1], ka.y, d1);
                FMA2(d2, q2[2 * c + 2], kb.x, d2);
                FMA2(d3, q2[2 * c + 3], kb.y, d3);
            }
            float2 f0 = *(float2*)&d0, f1 = *(float2*)&d1;
            float2 f2 = *(float2*)&d2, f3 = *(float2*)&d3;
            s[j] = ((f0.x + f0.y) + (f1.x + f1.y)) + ((f2.x + f2.y) + (f3.x + f3.y));
            mt = fmaxf(mt, s[j]);
        }

        // ---- online softmax rescale ----
        float mnew = fmaxf(m, mt);
        float corr = __expf(m - mnew);
        l *= corr;
        {
            ull c2 = pack2(corr, corr);
#pragma unroll
            for (int i = 0; i < 32; i++) MUL2(acc[i], acc[i], c2);
        }

        // ---- P @ V ----
#pragma unroll
        for (int j = 0; j < TK; j++) {
            float p = __expf(s[j] - mnew);
            l += p;
            ull pp = pack2(p, p);
            const ulonglong2* V2 = (const ulonglong2*)Vsh[cur][j];
#pragma unroll
            for (int c = 0; c < 16; c++) {
                ulonglong2 vv = V2[c];
                FMA2(acc[2 * c + 0], pp, vv.x, acc[2 * c + 0]);
                FMA2(acc[2 * c + 1], pp, vv.y, acc[2 * c + 1]);
            }
        }
        m = mnew;

        CP_WAIT0();
        __syncthreads();
    }

    float inv = 1.f / l;
    ull inv2 = pack2(inv, inv);
    ull* op = (ull*)(g_attn + (size_t)q * D_DIM + h * HDIM);
#pragma unroll
    for (int i = 0; i < 32; i++) {
        MUL2(acc[i], acc[i], inv2);
        op[i] = acc[i];
    }
}

// ---------------------------------------------------------------------------
extern "C" void kernel_launch(void* const* d_in, const int* in_sizes, int n_in,
                              void* d_out, int out_size)
{
    const float* utter = (const float*)d_in[0];
    const float* rctx  = (const float*)d_in[1];
    const float* mem   = (const float*)d_in[2];
    const float* lck   = (const float*)d_in[3];
    const float* lcv   = (const float*)d_in[4];
    const float* Wq    = (const float*)d_in[5];
    const float* bq    = (const float*)d_in[6];
    const float* Wkv   = (const float*)d_in[7];
    const float* bkv   = (const float*)d_in[8];
    const float* Wo    = (const float*)d_in[9];
    const float* bo    = (const float*)d_in[10];

    float* out = (float*)d_out;                       // [2304, 1024]
    float* key = out + (size_t)QLEN * D_DIM;          // [3840, 1024]
    float* val = key + (size_t)KVLEN * D_DIM;         // [3840, 1024]

    // 1) query projection
    gemm_tf32<0><<<dim3(D_DIM / 64, QLEN / 128), 128>>>(
        utter, rctx, nullptr, Wq, bq, nullptr, nullptr);

    // 2) kv projection -> scatter into key/value
    gemm_tf32<1><<<dim3(2 * D_DIM / 64, (MR + U_LEN) / 128), 128>>>(
        utter, rctx, mem, Wkv, bkv, key, val);

    // 3) left-context splice (contiguous)
    cudaMemcpyAsync(key + (size_t)MR * D_DIM, lck,
                    (size_t)L_LEN * D_DIM * sizeof(float),
                    cudaMemcpyDeviceToDevice, 0);
    cudaMemcpyAsync(val + (size_t)MR * D_DIM, lcv,
                    (size_t)L_LEN * D_DIM * sizeof(float),
                    cudaMemcpyDeviceToDevice, 0);

    // 4) attention
    attn_kernel<<<dim3(NHEAD, QLEN / BQ), BQ>>>(key, val);

    // 5) output projection
    gemm_tf32<2><<<dim3(D_DIM / 64, QLEN / 128), 128>>>(
        nullptr, nullptr, nullptr, Wo, bo, out, nullptr);
}

// round 3
// speedup vs baseline: 4.1467x; 2.7420x over previous
#include <cuda_runtime.h>
#include <cuda_bf16.h>

// Problem dims
#define U_LEN 2048
#define R_LEN 256
#define L_LEN 1024
#define M_LEN 512
#define D_DIM 1024
#define NHEAD 16
#define HDIM  64
#define QLEN  (U_LEN + R_LEN)                   // 2304
#define KVLEN (M_LEN + R_LEN + L_LEN + U_LEN)   // 3840
#define MR    (M_LEN + R_LEN)                   // 768

typedef unsigned long long ull;

// Scratch (no cudaMalloc allowed)
__device__ float g_query[QLEN * D_DIM];
__device__ float g_attn [QLEN * D_DIM];

// ---------------------------------------------------------------------------
// helpers
// ---------------------------------------------------------------------------
__device__ __forceinline__ unsigned f2tf32(float f) {
    unsigned r;
    asm("cvt.rna.tf32.f32 %0, %1;" : "=r"(r) : "f"(f));
    return r;
}

__device__ __forceinline__ void mma_tf32(float* d, const unsigned* a, unsigned b0, unsigned b1) {
    asm volatile(
        "mma.sync.aligned.m16n8k8.row.col.f32.tf32.tf32.f32 "
        "{%0,%1,%2,%3}, {%4,%5,%6,%7}, {%8,%9}, {%0,%1,%2,%3};"
        : "+f"(d[0]), "+f"(d[1]), "+f"(d[2]), "+f"(d[3])
        : "r"(a[0]), "r"(a[1]), "r"(a[2]), "r"(a[3]), "r"(b0), "r"(b1));
}

__device__ __forceinline__ void cp16(void* s, const void* g) {
    unsigned sa = (unsigned)__cvta_generic_to_shared(s);
    asm volatile("cp.async.cg.shared.global [%0], [%1], 16;" :: "r"(sa), "l"(g));
}
#define CP_COMMIT() asm volatile("cp.async.commit_group;")
#define CP_WAIT0()  asm volatile("cp.async.wait_group 0;" ::: "memory")

// ---------------------------------------------------------------------------
// TF32 tensor-core GEMM: C[M,N] = gather(A)[M,K] @ W[N,K]^T + bias
// (unchanged from round 2 — known good)
// ---------------------------------------------------------------------------
template <int MODE>
__global__ __launch_bounds__(128)
void gemm_tf32(const float* __restrict__ A0,
               const float* __restrict__ A1,
               const float* __restrict__ A2,
               const float* __restrict__ W,
               const float* __restrict__ bias,
               float* __restrict__ C0,
               float* __restrict__ C1)
{
    __shared__ unsigned As[128][20];
    __shared__ unsigned Bs[64][20];

    const int tid  = threadIdx.x;
    const int lane = tid & 31;
    const int warp = tid >> 5;
    const int bm = blockIdx.y, bn = blockIdx.x;
    const int K = D_DIM, KT = K / 16;
    const int tig = lane & 3, grp = lane >> 2;

    const float* arow[4];
#pragma unroll
    for (int i = 0; i < 4; i++) {
        int row = bm * 128 + (tid >> 2) + 32 * i;
        if (MODE == 0) {
            arow[i] = (row < R_LEN) ? (A1 + (size_t)row * D_DIM)
                                    : (A0 + (size_t)(row - R_LEN) * D_DIM);
        } else if (MODE == 1) {
            arow[i] = (row < M_LEN) ? (A2 + (size_t)row * D_DIM)
                    : (row < MR)    ? (A1 + (size_t)(row - M_LEN) * D_DIM)
                                    : (A0 + (size_t)(row - MR) * D_DIM);
        } else {
            arow[i] = g_attn + (size_t)row * D_DIM;
        }
    }
    const float* wrow[2];
#pragma unroll
    for (int i = 0; i < 2; i++) {
        int row = bn * 64 + (tid >> 2) + 32 * i;
        wrow[i] = W + (size_t)row * K;
    }

    float acc[2][8][4];
#pragma unroll
    for (int mt = 0; mt < 2; mt++)
#pragma unroll
        for (int nt = 0; nt < 8; nt++)
#pragma unroll
            for (int i = 0; i < 4; i++) acc[mt][nt][i] = 0.f;

    float4 ra[4], rb[2];
    const int c4 = (tid & 3) * 4;

#pragma unroll
    for (int i = 0; i < 4; i++) ra[i] = *(const float4*)(arow[i] + c4);
#pragma unroll
    for (int i = 0; i < 2; i++) rb[i] = *(const float4*)(wrow[i] + c4);
#pragma unroll
    for (int i = 0; i < 4; i++) {
        int r = (tid >> 2) + 32 * i;
        As[r][c4] = f2tf32(ra[i].x); As[r][c4 + 1] = f2tf32(ra[i].y);
        As[r][c4 + 2] = f2tf32(ra[i].z); As[r][c4 + 3] = f2tf32(ra[i].w);
    }
#pragma unroll
    for (int i = 0; i < 2; i++) {
        int r = (tid >> 2) + 32 * i;
        Bs[r][c4] = f2tf32(rb[i].x); Bs[r][c4 + 1] = f2tf32(rb[i].y);
        Bs[r][c4 + 2] = f2tf32(rb[i].z); Bs[r][c4 + 3] = f2tf32(rb[i].w);
    }
    __syncthreads();

    for (int kt = 0; kt < KT; kt++) {
        if (kt + 1 < KT) {
            int k0 = (kt + 1) * 16;
#pragma unroll
            for (int i = 0; i < 4; i++) ra[i] = *(const float4*)(arow[i] + k0 + c4);
#pragma unroll
            for (int i = 0; i < 2; i++) rb[i] = *(const float4*)(wrow[i] + k0 + c4);
        }
#pragma unroll
        for (int ks = 0; ks < 2; ks++) {
            int kk = ks * 8;
            unsigned b[8][2];
#pragma unroll
            for (int nt = 0; nt < 8; nt++) {
                b[nt][0] = Bs[nt * 8 + grp][kk + tig];
                b[nt][1] = Bs[nt * 8 + grp][kk + tig + 4];
            }
#pragma unroll
            for (int mt = 0; mt < 2; mt++) {
                unsigned a[4];
                int r0 = warp * 32 + mt * 16 + grp;
                a[0] = As[r0][kk + tig];     a[1] = As[r0 + 8][kk + tig];
                a[2] = As[r0][kk + tig + 4]; a[3] = As[r0 + 8][kk + tig + 4];
#pragma unroll
                for (int nt = 0; nt < 8; nt++) mma_tf32(acc[mt][nt], a, b[nt][0], b[nt][1]);
            }
        }
        __syncthreads();
        if (kt + 1 < KT) {
#pragma unroll
            for (int i = 0; i < 4; i++) {
                int r = (tid >> 2) + 32 * i;
                As[r][c4] = f2tf32(ra[i].x); As[r][c4 + 1] = f2tf32(ra[i].y);
                As[r][c4 + 2] = f2tf32(ra[i].z); As[r][c4 + 3] = f2tf32(ra[i].w);
            }
#pragma unroll
            for (int i = 0; i < 2; i++) {
                int r = (tid >> 2) + 32 * i;
                Bs[r][c4] = f2tf32(rb[i].x); Bs[r][c4 + 1] = f2tf32(rb[i].y);
                Bs[r][c4 + 2] = f2tf32(rb[i].z); Bs[r][c4 + 3] = f2tf32(rb[i].w);
            }
            __syncthreads();
        }
    }

#pragma unroll
    for (int mt = 0; mt < 2; mt++) {
#pragma unroll
        for (int nt = 0; nt < 8; nt++) {
            int col = bn * 64 + nt * 8 + 2 * tig;
#pragma unroll
            for (int half = 0; half < 2; half++) {
                int row = bm * 128 + warp * 32 + mt * 16 + grp + half * 8;
                float v0 = acc[mt][nt][half * 2 + 0] + bias[col];
                float v1 = acc[mt][nt][half * 2 + 1] + bias[col + 1];
                if (MODE == 0) {
                    *(float2*)(g_query + (size_t)row * D_DIM + col) = make_float2(v0, v1);
                } else if (MODE == 1) {
                    int krow = (row < MR) ? row : row + L_LEN;
                    if (col < D_DIM)
                        *(float2*)(C0 + (size_t)krow * D_DIM + col) = make_float2(v0, v1);
                    else
                        *(float2*)(C1 + (size_t)krow * D_DIM + (col - D_DIM)) = make_float2(v0, v1);
                } else {
                    *(float2*)(C0 + (size_t)row * D_DIM + col) = make_float2(v0, v1);
                }
            }
        }
    }
}

// ---------------------------------------------------------------------------
// Tensor-core flash attention (tf32 mma for QK^T and P@V).
// Block: 256 threads (8 warps) = 128 q rows of one head. Warp w owns rows
// [w*16, w*16+16). K/V tiles of 64 keys, double-buffered cp.async.
// ---------------------------------------------------------------------------
#define AT_TK   64
#define AT_NT   (KVLEN / AT_TK)    // 60
#define KS_STR  68                  // floats per K row (pad: conflict-free)
#define VS_STR  72                  // floats per V row
#define PS_STR  72                  // floats per P row
#define SM_KS   0
#define SM_VS   (2 * 64 * KS_STR)
#define SM_PS   (SM_VS + 2 * 64 * VS_STR)
#define ATT_SMEM ((SM_PS + 8 * 16 * PS_STR) * 4)

__global__ __launch_bounds__(256, 2)
void attn_mma(const float* __restrict__ key,
              const float* __restrict__ value)
{
    extern __shared__ float sm[];
    float* Ks = sm + SM_KS;
    float* Vs = sm + SM_VS;
    float* Pw = sm + SM_PS + (threadIdx.x >> 5) * 16 * PS_STR;

    const int h   = blockIdx.x;
    const int qb  = blockIdx.y;
    const int tid = threadIdx.x;
    const int lane = tid & 31;
    const int w    = tid >> 5;
    const int grp  = lane >> 2;
    const int tig  = lane & 3;

    // ---- Q fragments (pre-scaled, tf32) ----
    unsigned qa[8][4];
    {
        const float* q0 = g_query + (size_t)(qb * 128 + w * 16 + grp) * D_DIM + h * HDIM;
        const float* q1 = q0 + 8 * D_DIM;
#pragma unroll
        for (int kb = 0; kb < 8; kb++) {
            qa[kb][0] = f2tf32(q0[kb * 8 + tig] * 0.125f);
            qa[kb][1] = f2tf32(q1[kb * 8 + tig] * 0.125f);
            qa[kb][2] = f2tf32(q0[kb * 8 + tig + 4] * 0.125f);
            qa[kb][3] = f2tf32(q1[kb * 8 + tig + 4] * 0.125f);
        }
    }

    float acc[8][4];
#pragma unroll
    for (int nt = 0; nt < 8; nt++)
#pragma unroll
        for (int i = 0; i < 4; i++) acc[nt][i] = 0.f;
    float m0 = -1e30f, m1 = -1e30f, l0 = 0.f, l1 = 0.f;

    const float* kbase = key   + (size_t)h * HDIM;
    const float* vbase = value + (size_t)h * HDIM;

    // tile loader: 1024 16B chunks for each of K,V; 256 threads x 4
    // chunk idx -> row = idx>>4, col4 = idx&15
    // prologue: tile 0 -> buf 0
#pragma unroll
    for (int i = 0; i < 4; i++) {
        int idx = tid + i * 256;
        int r = idx >> 4, c = idx & 15;
        cp16(&Ks[r * KS_STR + c * 4], kbase + (size_t)r * D_DIM + c * 4);
        cp16(&Vs[r * VS_STR + c * 4], vbase + (size_t)r * D_DIM + c * 4);
    }
    CP_COMMIT();
    CP_WAIT0();
    __syncthreads();

    for (int t = 0; t < AT_NT; t++) {
        const int cur = t & 1;
        const float* Kc = Ks + cur * 64 * KS_STR;
        const float* Vc = Vs + cur * 64 * VS_STR;

        // prefetch next tile
        if (t + 1 < AT_NT) {
            const float* kn = kbase + (size_t)(t + 1) * AT_TK * D_DIM;
            const float* vn = vbase + (size_t)(t + 1) * AT_TK * D_DIM;
            float* Kn = Ks + (cur ^ 1) * 64 * KS_STR;
            float* Vn = Vs + (cur ^ 1) * 64 * VS_STR;
#pragma unroll
            for (int i = 0; i < 4; i++) {
                int idx = tid + i * 256;
                int r = idx >> 4, c = idx & 15;
                cp16(&Kn[r * KS_STR + c * 4], kn + (size_t)r * D_DIM + c * 4);
                cp16(&Vn[r * VS_STR + c * 4], vn + (size_t)r * D_DIM + c * 4);
            }
        }
        CP_COMMIT();

        // ---- S = Q K^T (16 x 64 per warp) ----
        float s[8][4];
#pragma unroll
        for (int nt = 0; nt < 8; nt++)
#pragma unroll
            for (int i = 0; i < 4; i++) s[nt][i] = 0.f;
#pragma unroll
        for (int kb = 0; kb < 8; kb++) {
#pragma unroll
            for (int nt = 0; nt < 8; nt++) {
                unsigned b0 = __float_as_uint(Kc[(nt * 8 + grp) * KS_STR + kb * 8 + tig]);
                unsigned b1 = __float_as_uint(Kc[(nt * 8 + grp) * KS_STR + kb * 8 + tig + 4]);
                mma_tf32(s[nt], qa[kb], b0, b1);
            }
        }

        // ---- online softmax ----
        float mt0 = -1e30f, mt1 = -1e30f;
#pragma unroll
        for (int nt = 0; nt < 8; nt++) {
            mt0 = fmaxf(mt0, fmaxf(s[nt][0], s[nt][1]));
            mt1 = fmaxf(mt1, fmaxf(s[nt][2], s[nt][3]));
        }
        mt0 = fmaxf(mt0, __shfl_xor_sync(0xffffffff, mt0, 1));
        mt0 = fmaxf(mt0, __shfl_xor_sync(0xffffffff, mt0, 2));
        mt1 = fmaxf(mt1, __shfl_xor_sync(0xffffffff, mt1, 1));
        mt1 = fmaxf(mt1, __shfl_xor_sync(0xffffffff, mt1, 2));

        float mn0 = fmaxf(m0, mt0), mn1 = fmaxf(m1, mt1);
        float c0 = __expf(m0 - mn0), c1 = __expf(m1 - mn1);
        l0 *= c0; l1 *= c1;
        m0 = mn0; m1 = mn1;

#pragma unroll
        for (int nt = 0; nt < 8; nt++) {
            float p00 = __expf(s[nt][0] - mn0);
            float p01 = __expf(s[nt][1] - mn0);
            float p10 = __expf(s[nt][2] - mn1);
            float p11 = __expf(s[nt][3] - mn1);
            l0 += p00 + p01;
            l1 += p10 + p11;
            *(float2*)&Pw[grp * PS_STR + nt * 8 + 2 * tig]       = make_float2(p00, p01);
            *(float2*)&Pw[(grp + 8) * PS_STR + nt * 8 + 2 * tig] = make_float2(p10, p11);
            acc[nt][0] *= c0; acc[nt][1] *= c0;
            acc[nt][2] *= c1; acc[nt][3] *= c1;
        }
        __syncwarp();

        // ---- acc += P @ V ----
#pragma unroll
        for (int kb = 0; kb < 8; kb++) {
            unsigned a[4];
            a[0] = __float_as_uint(Pw[grp * PS_STR + kb * 8 + tig]);
            a[1] = __float_as_uint(Pw[(grp + 8) * PS_STR + kb * 8 + tig]);
            a[2] = __float_as_uint(Pw[grp * PS_STR + kb * 8 + tig + 4]);
            a[3] = __float_as_uint(Pw[(grp + 8) * PS_STR + kb * 8 + tig + 4]);
#pragma unroll
            for (int nt = 0; nt < 8; nt++) {
                unsigned b0 = __float_as_uint(Vc[(kb * 8 + tig) * VS_STR + nt * 8 + grp]);
                unsigned b1 = __float_as_uint(Vc[(kb * 8 + tig + 4) * VS_STR + nt * 8 + grp]);
                mma_tf32(acc[nt], a, b0, b1);
            }
        }

        CP_WAIT0();
        __syncthreads();
    }

    // ---- finalize ----
    l0 += __shfl_xor_sync(0xffffffff, l0, 1);
    l0 += __shfl_xor_sync(0xffffffff, l0, 2);
    l1 += __shfl_xor_sync(0xffffffff, l1, 1);
    l1 += __shfl_xor_sync(0xffffffff, l1, 2);
    float inv0 = 1.f / l0, inv1 = 1.f / l1;

    int r0 = qb * 128 + w * 16 + grp;
    float* o0 = g_attn + (size_t)r0 * D_DIM + h * HDIM;
    float* o1 = o0 + 8 * D_DIM;
#pragma unroll
    for (int nt = 0; nt < 8; nt++) {
        int col = nt * 8 + 2 * tig;
        *(float2*)(o0 + col) = make_float2(acc[nt][0] * inv0, acc[nt][1] * inv0);
        *(float2*)(o1 + col) = make_float2(acc[nt][2] * inv1, acc[nt][3] * inv1);
    }
}

// ---------------------------------------------------------------------------
extern "C" void kernel_launch(void* const* d_in, const int* in_sizes, int n_in,
                              void* d_out, int out_size)
{
    const float* utter = (const float*)d_in[0];
    const float* rctx  = (const float*)d_in[1];
    const float* mem   = (const float*)d_in[2];
    const float* lck   = (const float*)d_in[3];
    const float* lcv   = (const float*)d_in[4];
    const float* Wq    = (const float*)d_in[5];
    const float* bq    = (const float*)d_in[6];
    const float* Wkv   = (const float*)d_in[7];
    const float* bkv   = (const float*)d_in[8];
    const float* Wo    = (const float*)d_in[9];
    const float* bo    = (const float*)d_in[10];

    float* out = (float*)d_out;                       // [2304, 1024]
    float* key = out + (size_t)QLEN * D_DIM;          // [3840, 1024]
    float* val = key + (size_t)KVLEN * D_DIM;         // [3840, 1024]

    cudaFuncSetAttribute(attn_mma, cudaFuncAttributeMaxDynamicSharedMemorySize, ATT_SMEM);

    // 1) query projection
    gemm_tf32<0><<<dim3(D_DIM / 64, QLEN / 128), 128>>>(
        utter, rctx, nullptr, Wq, bq, nullptr, nullptr);

    // 2) kv projection -> scatter into key/value
    gemm_tf32<1><<<dim3(2 * D_DIM / 64, (MR + U_LEN) / 128), 128>>>(
        utter, rctx, mem, Wkv, bkv, key, val);

    // 3) left-context splice (contiguous)
    cudaMemcpyAsync(key + (size_t)MR * D_DIM, lck,
                    (size_t)L_LEN * D_DIM * sizeof(float),
                    cudaMemcpyDeviceToDevice, 0);
    cudaMemcpyAsync(val + (size_t)MR * D_DIM, lcv,
                    (size_t)L_LEN * D_DIM * sizeof(float),
                    cudaMemcpyDeviceToDevice, 0);

    // 4) attention (tensor-core flash)
    attn_mma<<<dim3(NHEAD, QLEN / 128), 256, ATT_SMEM>>>(key, val);

    // 5) output projection
    gemm_tf32<2><<<dim3(D_DIM / 64, QLEN / 128), 128>>>(
        nullptr, nullptr, nullptr, Wo, bo, out, nullptr);
}